// round 7
// baseline (speedup 1.0000x reference)
#include <cuda_runtime.h>
#include <cuda_bf16.h>
#include <cstddef>

// MultiNetworkRNN: N_NET=32, N_UNITS=2048, N_EXC=1638, N_INH=410
// out[n,q] = r + DT*((relu(total)-r)/TAU)
// total[:,0:NE]  = r_e @ W_ee + r_i @ W_ie + unit_input_e
// total[:,NE:NU] = r_e @ W_ei + r_i @ W_ii + unit_input_i + inter
// inter[i,a] = sum_{j,b} W_inter[i,j,a,b] * r[i, NE+b]

#define N_NET 32
#define NU 2048
#define NE 1638
#define NI 410
#define DT 0.01f
#define TAU 0.1f

#define P_SLICES 8
#define P_PER_SLICE (NU / P_SLICES)             // 256

#define INTER_BLOCKS (N_NET * NI)               // 13120
// Role A: E outputs (width NE): 4 q-tiles (3 full 512-wide + 1 ragged 102-wide)
#define A_TILES 4
#define A_BLOCKS (N_NET * P_SLICES * A_TILES)   // 1024
// Role B: I outputs (width NI): 1 predicated 512-wide tile
#define B_BLOCKS (N_NET * P_SLICES)             // 256
#define TOTAL_BLOCKS (INTER_BLOCKS + A_BLOCKS + B_BLOCKS)  // 14400

__device__ float g_inter[N_NET * NI];
__device__ float g_partial[P_SLICES * N_NET * NU];   // [slice][net][q], 2 MB

// ---------------------------------------------------------------------------
// Fused streaming kernel:
//   blocks [0, INTER_BLOCKS)    : inter[i,a]
//   next A_BLOCKS               : E-output partial GEMV (2048B-wide row reads)
//   next B_BLOCKS               : I-output partial GEMV
// Wide row footprints cut sector-straddle overfetch from ~6.25% to ~1.6%.
// ---------------------------------------------------------------------------
__global__ void __launch_bounds__(128) fused_kernel(
    const float* __restrict__ r,
    const float* __restrict__ W_ee,
    const float* __restrict__ W_ei,
    const float* __restrict__ W_ie,
    const float* __restrict__ W_ii,
    const float* __restrict__ W_inter)
{
    __shared__ float rs[NI + 8];
    __shared__ float red[4];

    const int bx  = blockIdx.x;
    const int tid = threadIdx.x;

    if (bx < INTER_BLOCKS) {
        // ----------------- inter role -----------------
        const int a = bx % NI;
        const int i = bx / NI;

        const float* ri = r + (size_t)i * NU + NE;
        for (int b = tid; b < NI; b += 128) rs[b] = ri[b];
        __syncthreads();

        const float* base = W_inter + (size_t)i * N_NET * (NI * NI) + (size_t)a * NI;

        float acc = 0.f;
        for (int t = tid; t < NI / 2; t += 128) {
            const float x = rs[2 * t];
            const float y = rs[2 * t + 1];
            #pragma unroll 8
            for (int j = 0; j < N_NET; ++j) {
                const float2 w = *(const float2*)(base + (size_t)j * (NI * NI) + 2 * t);
                acc = fmaf(w.x, x, acc);
                acc = fmaf(w.y, y, acc);
            }
        }

        #pragma unroll
        for (int o = 16; o > 0; o >>= 1)
            acc += __shfl_down_sync(0xFFFFFFFFu, acc, o);
        if ((tid & 31) == 0) red[tid >> 5] = acc;
        __syncthreads();
        if (tid == 0)
            g_inter[i * NI + a] = red[0] + red[1] + red[2] + red[3];
    } else if (bx < INTER_BLOCKS + A_BLOCKS) {
        // ----------------- Role A: E-output partials -----------------
        const int bx2 = bx - INTER_BLOCKS;
        const int ta  = bx2 & 3;            // q tile (4)
        const int ps  = (bx2 >> 2) & 7;     // p slice (8)
        const int n   = bx2 >> 5;           // net (32)

        const int pa = ps * P_PER_SLICE;
        const int pb = pa + P_PER_SLICE;
        const int pe = (pb < NE) ? pb : NE;       // end of E-row range
        const int p0 = (pa > NE) ? pa : NE;       // start of I-row range

        rs[tid]       = r[(size_t)n * NU + pa + tid];
        rs[tid + 128] = r[(size_t)n * NU + pa + tid + 128];
        __syncthreads();

        if (ta < 3) {
            // full 512-wide tile: 4 columns per thread, 2-row load batching.
            // All (pa,pe) / (p0,pb) ranges have even length; empty when inverted.
            const int q0 = ta * 512;
            const float* bE = W_ee + (size_t)n * NE * NE + q0 + tid;
            const float* bI = W_ie + (size_t)n * NI * NE + q0 + tid;

            float a0 = 0.f, a1 = 0.f, a2 = 0.f, a3 = 0.f;

            for (int p = pa; p < pe; p += 2) {
                const float* r0 = bE + (size_t)p * NE;
                const float* r1 = r0 + NE;
                const float w00 = r0[0],   w01 = r0[128], w02 = r0[256], w03 = r0[384];
                const float w10 = r1[0],   w11 = r1[128], w12 = r1[256], w13 = r1[384];
                const float x0 = rs[p - pa], x1 = rs[p - pa + 1];
                a0 = fmaf(w00, x0, a0); a1 = fmaf(w01, x0, a1);
                a2 = fmaf(w02, x0, a2); a3 = fmaf(w03, x0, a3);
                a0 = fmaf(w10, x1, a0); a1 = fmaf(w11, x1, a1);
                a2 = fmaf(w12, x1, a2); a3 = fmaf(w13, x1, a3);
            }
            for (int p = p0; p < pb; p += 2) {
                const float* r0 = bI + (size_t)(p - NE) * NE;
                const float* r1 = r0 + NE;
                const float w00 = r0[0],   w01 = r0[128], w02 = r0[256], w03 = r0[384];
                const float w10 = r1[0],   w11 = r1[128], w12 = r1[256], w13 = r1[384];
                const float x0 = rs[p - pa], x1 = rs[p - pa + 1];
                a0 = fmaf(w00, x0, a0); a1 = fmaf(w01, x0, a1);
                a2 = fmaf(w02, x0, a2); a3 = fmaf(w03, x0, a3);
                a0 = fmaf(w10, x1, a0); a1 = fmaf(w11, x1, a1);
                a2 = fmaf(w12, x1, a2); a3 = fmaf(w13, x1, a3);
            }

            float* dst = &g_partial[((size_t)ps * N_NET + n) * NU + q0 + tid];
            dst[0]   = a0;
            dst[128] = a1;
            dst[256] = a2;
            dst[384] = a3;
        } else if (tid < NE - 1536) {
            // ragged tile: columns [1536, 1638), 1 col/thread, 8-row batching.
            // Sequential p cursor: loops are naturally empty when ranges invert.
            const int q = 1536 + tid;
            const float* colE = W_ee + (size_t)n * NE * NE + q;
            const float* colI = W_ie + (size_t)n * NI * NE + q;

            float acc = 0.f;
            int p = pa;
            for (; p + 8 <= pe; p += 8) {
                const float w0 = colE[(size_t)(p + 0) * NE];
                const float w1 = colE[(size_t)(p + 1) * NE];
                const float w2 = colE[(size_t)(p + 2) * NE];
                const float w3 = colE[(size_t)(p + 3) * NE];
                const float w4 = colE[(size_t)(p + 4) * NE];
                const float w5 = colE[(size_t)(p + 5) * NE];
                const float w6 = colE[(size_t)(p + 6) * NE];
                const float w7 = colE[(size_t)(p + 7) * NE];
                const int t = p - pa;
                acc = fmaf(w0, rs[t + 0], acc); acc = fmaf(w1, rs[t + 1], acc);
                acc = fmaf(w2, rs[t + 2], acc); acc = fmaf(w3, rs[t + 3], acc);
                acc = fmaf(w4, rs[t + 4], acc); acc = fmaf(w5, rs[t + 5], acc);
                acc = fmaf(w6, rs[t + 6], acc); acc = fmaf(w7, rs[t + 7], acc);
            }
            for (; p < pe; ++p)
                acc = fmaf(colE[(size_t)p * NE], rs[p - pa], acc);

            p = p0;
            for (; p + 8 <= pb; p += 8) {
                const float w0 = colI[(size_t)(p - NE + 0) * NE];
                const float w1 = colI[(size_t)(p - NE + 1) * NE];
                const float w2 = colI[(size_t)(p - NE + 2) * NE];
                const float w3 = colI[(size_t)(p - NE + 3) * NE];
                const float w4 = colI[(size_t)(p - NE + 4) * NE];
                const float w5 = colI[(size_t)(p - NE + 5) * NE];
                const float w6 = colI[(size_t)(p - NE + 6) * NE];
                const float w7 = colI[(size_t)(p - NE + 7) * NE];
                const int t = p - pa;
                acc = fmaf(w0, rs[t + 0], acc); acc = fmaf(w1, rs[t + 1], acc);
                acc = fmaf(w2, rs[t + 2], acc); acc = fmaf(w3, rs[t + 3], acc);
                acc = fmaf(w4, rs[t + 4], acc); acc = fmaf(w5, rs[t + 5], acc);
                acc = fmaf(w6, rs[t + 6], acc); acc = fmaf(w7, rs[t + 7], acc);
            }
            for (; p < pb; ++p)
                acc = fmaf(colI[(size_t)(p - NE) * NE], rs[p - pa], acc);

            g_partial[((size_t)ps * N_NET + n) * NU + q] = acc;
        }
    } else {
        // ----------------- Role B: I-output partials -----------------
        const int bx2 = bx - INTER_BLOCKS - A_BLOCKS;
        const int ps  = bx2 & 7;            // p slice (8)
        const int n   = bx2 >> 3;           // net (32)

        const int pa = ps * P_PER_SLICE;
        const int pb = pa + P_PER_SLICE;
        const int pe = (pb < NE) ? pb : NE;
        const int p0 = (pa > NE) ? pa : NE;

        rs[tid]       = r[(size_t)n * NU + pa + tid];
        rs[tid + 128] = r[(size_t)n * NU + pa + tid + 128];
        __syncthreads();

        const bool v3 = (tid + 384) < NI;   // tid < 26
        // Clamp the 4th-column offset so the load is ALWAYS in bounds
        // (no reliance on predication); a3 is only stored when v3.
        const int o3 = v3 ? 384 : 0;
        const float* bE = W_ei + (size_t)n * NE * NI + tid;
        const float* bI = W_ii + (size_t)n * NI * NI + tid;

        float a0 = 0.f, a1 = 0.f, a2 = 0.f, a3 = 0.f;

        for (int p = pa; p < pe; p += 2) {
            const float* r0 = bE + (size_t)p * NI;
            const float* r1 = r0 + NI;
            const float w00 = r0[0],   w01 = r0[128], w02 = r0[256], w03 = r0[o3];
            const float w10 = r1[0],   w11 = r1[128], w12 = r1[256], w13 = r1[o3];
            const float x0 = rs[p - pa], x1 = rs[p - pa + 1];
            a0 = fmaf(w00, x0, a0); a1 = fmaf(w01, x0, a1);
            a2 = fmaf(w02, x0, a2); a3 = fmaf(w03, x0, a3);
            a0 = fmaf(w10, x1, a0); a1 = fmaf(w11, x1, a1);
            a2 = fmaf(w12, x1, a2); a3 = fmaf(w13, x1, a3);
        }
        for (int p = p0; p < pb; p += 2) {
            const float* r0 = bI + (size_t)(p - NE) * NI;
            const float* r1 = r0 + NI;
            const float w00 = r0[0],   w01 = r0[128], w02 = r0[256], w03 = r0[o3];
            const float w10 = r1[0],   w11 = r1[128], w12 = r1[256], w13 = r1[o3];
            const float x0 = rs[p - pa], x1 = rs[p - pa + 1];
            a0 = fmaf(w00, x0, a0); a1 = fmaf(w01, x0, a1);
            a2 = fmaf(w02, x0, a2); a3 = fmaf(w03, x0, a3);
            a0 = fmaf(w10, x1, a0); a1 = fmaf(w11, x1, a1);
            a2 = fmaf(w12, x1, a2); a3 = fmaf(w13, x1, a3);
        }

        float* dst = &g_partial[((size_t)ps * N_NET + n) * NU + NE + tid];
        dst[0]   = a0;
        dst[128] = a1;
        dst[256] = a2;
        if (v3) dst[384] = a3;
    }

#if __CUDA_ARCH__ >= 900
    cudaTriggerProgrammaticLaunchCompletion();
#endif
}

// ---------------------------------------------------------------------------
// Reduce 8 partials + unit_input (+inter for inhibitory) + epilogue.
// PDL-launched: prefetch primary-independent inputs, then grid-dep sync.
// ---------------------------------------------------------------------------
__global__ void __launch_bounds__(1024) reduce_kernel(
    const float* __restrict__ unit_input,
    const float* __restrict__ r,
    float* __restrict__ out)
{
    const int idx = blockIdx.x * 1024 + threadIdx.x;   // 0..65535
    const int n = idx >> 11;
    const int q = idx & 2047;

    const float ui = unit_input[idx];
    const float rv = r[idx];

#if __CUDA_ARCH__ >= 900
    cudaGridDependencySynchronize();
#endif

    float acc = 0.f;
    #pragma unroll
    for (int s = 0; s < P_SLICES; ++s)
        acc += g_partial[((size_t)s * N_NET + n) * NU + q];

    acc += ui;
    if (q >= NE) acc += g_inter[n * NI + (q - NE)];

    const float phi = fmaxf(acc, 0.f);
    out[idx] = rv + DT * ((phi - rv) / TAU);
}

extern "C" void kernel_launch(void* const* d_in, const int* in_sizes, int n_in,
                              void* d_out, int out_size)
{
    const float* unit_input = (const float*)d_in[0];
    const float* r          = (const float*)d_in[1];
    const float* W_ee       = (const float*)d_in[2];
    const float* W_ei       = (const float*)d_in[3];
    const float* W_ie       = (const float*)d_in[4];
    const float* W_ii       = (const float*)d_in[5];
    const float* W_inter    = (const float*)d_in[6];
    float* out = (float*)d_out;

    fused_kernel<<<TOTAL_BLOCKS, 128>>>(r, W_ee, W_ei, W_ie, W_ii, W_inter);

    cudaLaunchConfig_t cfg = {};
    cfg.gridDim  = dim3(64, 1, 1);
    cfg.blockDim = dim3(1024, 1, 1);
    cfg.dynamicSmemBytes = 0;
    cfg.stream = 0;
    cudaLaunchAttribute attrs[1];
    attrs[0].id = cudaLaunchAttributeProgrammaticStreamSerialization;
    attrs[0].val.programmaticStreamSerializationAllowed = 1;
    cfg.attrs = attrs;
    cfg.numAttrs = 1;
    cudaLaunchKernelEx(&cfg, reduce_kernel, unit_input, r, out);
}

// round 8
// speedup vs baseline: 1.1851x; 1.1851x over previous
#include <cuda_runtime.h>
#include <cuda_bf16.h>
#include <cstddef>

// MultiNetworkRNN: N_NET=32, N_UNITS=2048, N_EXC=1638, N_INH=410
// out[n,q] = r + DT*((relu(total)-r)/TAU)
// total[:,0:NE]  = r_e @ W_ee + r_i @ W_ie + unit_input_e
// total[:,NE:NU] = r_e @ W_ei + r_i @ W_ii + unit_input_i + inter
// inter[i,a] = sum_{j,b} W_inter[i,j,a,b] * r[i, NE+b]
//
// R5 structure (best measured: 186.3us):
//  - fused streaming kernel (inter + partial GEMV), 17216 blocks, ~6.5 TB/s
//  - PDL-overlapped reduce/epilogue kernel

#define N_NET 32
#define NU 2048
#define NE 1638
#define NI 410
#define DT 0.01f
#define TAU 0.1f

#define P_SLICES 8
#define P_PER_SLICE (NU / P_SLICES)             // 256

#define INTER_BLOCKS (N_NET * NI)               // 13120
#define PARTIAL_BLOCKS (16 * P_SLICES * N_NET)  // 4096
#define TOTAL_BLOCKS (INTER_BLOCKS + PARTIAL_BLOCKS)

__device__ float g_inter[N_NET * NI];
__device__ float g_partial[P_SLICES * N_NET * NU];   // [slice][net][q], 2 MB

// ---------------------------------------------------------------------------
// Fused streaming kernel:
//   blocks [0, INTER_BLOCKS)            : inter[i,a]
//   blocks [INTER_BLOCKS, TOTAL_BLOCKS) : partial GEMV sums
// ---------------------------------------------------------------------------
__global__ void __launch_bounds__(128) fused_kernel(
    const float* __restrict__ r,
    const float* __restrict__ W_ee,
    const float* __restrict__ W_ei,
    const float* __restrict__ W_ie,
    const float* __restrict__ W_ii,
    const float* __restrict__ W_inter)
{
    __shared__ float rs[NI + 8];
    __shared__ float red[4];

    const int bx  = blockIdx.x;
    const int tid = threadIdx.x;

    if (bx < INTER_BLOCKS) {
        // ----------------- inter role -----------------
        const int a = bx % NI;
        const int i = bx / NI;

        const float* ri = r + (size_t)i * NU + NE;
        for (int b = tid; b < NI; b += 128) rs[b] = ri[b];
        __syncthreads();

        const float* base = W_inter + (size_t)i * N_NET * (NI * NI) + (size_t)a * NI;

        float acc = 0.f;
        for (int t = tid; t < NI / 2; t += 128) {
            const float x = rs[2 * t];
            const float y = rs[2 * t + 1];
            #pragma unroll 8
            for (int j = 0; j < N_NET; ++j) {
                const float2 w = *(const float2*)(base + (size_t)j * (NI * NI) + 2 * t);
                acc = fmaf(w.x, x, acc);
                acc = fmaf(w.y, y, acc);
            }
        }

        #pragma unroll
        for (int o = 16; o > 0; o >>= 1)
            acc += __shfl_down_sync(0xFFFFFFFFu, acc, o);
        if ((tid & 31) == 0) red[tid >> 5] = acc;
        __syncthreads();
        if (tid == 0)
            g_inter[i * NI + a] = red[0] + red[1] + red[2] + red[3];
    } else {
        // ----------------- partial GEMV role -----------------
        const int bx2 = bx - INTER_BLOCKS;
        const int qt  = bx2 & 15;          // q tile (16)
        const int ps  = (bx2 >> 4) & 7;    // p slice (8)
        const int n   = bx2 >> 7;          // net (32)

        const int q  = qt * 128 + tid;     // 0..2047
        const int pa = ps * P_PER_SLICE;
        const int pb = pa + P_PER_SLICE;

        rs[tid]       = r[(size_t)n * NU + pa + tid];
        rs[tid + 128] = r[(size_t)n * NU + pa + tid + 128];
        __syncthreads();

        const float* colE;
        const float* colI;
        int stride;
        if (q < NE) {
            stride = NE;
            colE = W_ee + (size_t)n * NE * NE + q;
            colI = W_ie + (size_t)n * NI * NE + q;
        } else {
            const int qq = q - NE;
            stride = NI;
            colE = W_ei + (size_t)n * NE * NI + qq;
            colI = W_ii + (size_t)n * NI * NI + qq;
        }

        float acc = 0.f;

        // rows p in [pa, min(pb, NE)) from the E-row matrix
        {
            const int pe = (pb < NE) ? pb : NE;
            int p = pa;
            for (; p + 8 <= pe; p += 8) {
                const float w0 = colE[(size_t)(p + 0) * stride];
                const float w1 = colE[(size_t)(p + 1) * stride];
                const float w2 = colE[(size_t)(p + 2) * stride];
                const float w3 = colE[(size_t)(p + 3) * stride];
                const float w4 = colE[(size_t)(p + 4) * stride];
                const float w5 = colE[(size_t)(p + 5) * stride];
                const float w6 = colE[(size_t)(p + 6) * stride];
                const float w7 = colE[(size_t)(p + 7) * stride];
                const int t = p - pa;
                acc = fmaf(w0, rs[t + 0], acc);
                acc = fmaf(w1, rs[t + 1], acc);
                acc = fmaf(w2, rs[t + 2], acc);
                acc = fmaf(w3, rs[t + 3], acc);
                acc = fmaf(w4, rs[t + 4], acc);
                acc = fmaf(w5, rs[t + 5], acc);
                acc = fmaf(w6, rs[t + 6], acc);
                acc = fmaf(w7, rs[t + 7], acc);
            }
            for (; p < pe; ++p)
                acc = fmaf(colE[(size_t)p * stride], rs[p - pa], acc);
        }

        // rows p in [max(pa, NE), pb) from the I-row matrix
        {
            const int p0 = (pa > NE) ? pa : NE;
            int p = p0;
            for (; p + 8 <= pb; p += 8) {
                const float w0 = colI[(size_t)(p - NE + 0) * stride];
                const float w1 = colI[(size_t)(p - NE + 1) * stride];
                const float w2 = colI[(size_t)(p - NE + 2) * stride];
                const float w3 = colI[(size_t)(p - NE + 3) * stride];
                const float w4 = colI[(size_t)(p - NE + 4) * stride];
                const float w5 = colI[(size_t)(p - NE + 5) * stride];
                const float w6 = colI[(size_t)(p - NE + 6) * stride];
                const float w7 = colI[(size_t)(p - NE + 7) * stride];
                const int t = p - pa;
                acc = fmaf(w0, rs[t + 0], acc);
                acc = fmaf(w1, rs[t + 1], acc);
                acc = fmaf(w2, rs[t + 2], acc);
                acc = fmaf(w3, rs[t + 3], acc);
                acc = fmaf(w4, rs[t + 4], acc);
                acc = fmaf(w5, rs[t + 5], acc);
                acc = fmaf(w6, rs[t + 6], acc);
                acc = fmaf(w7, rs[t + 7], acc);
            }
            for (; p < pb; ++p)
                acc = fmaf(colI[(size_t)(p - NE) * stride], rs[p - pa], acc);
        }

        g_partial[((size_t)ps * N_NET + n) * NU + q] = acc;
    }

#if __CUDA_ARCH__ >= 900
    cudaTriggerProgrammaticLaunchCompletion();
#endif
}

// ---------------------------------------------------------------------------
// Reduce 8 partials + unit_input (+inter for inhibitory) + epilogue.
// PDL-launched: prefetch primary-independent inputs, then grid-dep sync.
// ---------------------------------------------------------------------------
__global__ void __launch_bounds__(1024) reduce_kernel(
    const float* __restrict__ unit_input,
    const float* __restrict__ r,
    float* __restrict__ out)
{
    const int idx = blockIdx.x * 1024 + threadIdx.x;   // 0..65535
    const int n = idx >> 11;
    const int q = idx & 2047;

    const float ui = unit_input[idx];
    const float rv = r[idx];

#if __CUDA_ARCH__ >= 900
    cudaGridDependencySynchronize();
#endif

    float acc = 0.f;
    #pragma unroll
    for (int s = 0; s < P_SLICES; ++s)
        acc += g_partial[((size_t)s * N_NET + n) * NU + q];

    acc += ui;
    if (q >= NE) acc += g_inter[n * NI + (q - NE)];

    const float phi = fmaxf(acc, 0.f);
    out[idx] = rv + DT * ((phi - rv) / TAU);
}

extern "C" void kernel_launch(void* const* d_in, const int* in_sizes, int n_in,
                              void* d_out, int out_size)
{
    const float* unit_input = (const float*)d_in[0];
    const float* r          = (const float*)d_in[1];
    const float* W_ee       = (const float*)d_in[2];
    const float* W_ei       = (const float*)d_in[3];
    const float* W_ie       = (const float*)d_in[4];
    const float* W_ii       = (const float*)d_in[5];
    const float* W_inter    = (const float*)d_in[6];
    float* out = (float*)d_out;

    fused_kernel<<<TOTAL_BLOCKS, 128>>>(r, W_ee, W_ei, W_ie, W_ii, W_inter);

    cudaLaunchConfig_t cfg = {};
    cfg.gridDim  = dim3(64, 1, 1);
    cfg.blockDim = dim3(1024, 1, 1);
    cfg.dynamicSmemBytes = 0;
    cfg.stream = 0;
    cudaLaunchAttribute attrs[1];
    attrs[0].id = cudaLaunchAttributeProgrammaticStreamSerialization;
    attrs[0].val.programmaticStreamSerializationAllowed = 1;
    cfg.attrs = attrs;
    cfg.numAttrs = 1;
    cudaLaunchKernelEx(&cfg, reduce_kernel, unit_input, r, out);
}

// round 9
// speedup vs baseline: 1.2201x; 1.0296x over previous
#include <cuda_runtime.h>
#include <cuda_bf16.h>
#include <cstddef>

// MultiNetworkRNN: N_NET=32, N_UNITS=2048, N_EXC=1638, N_INH=410
// out[n,q] = r + DT*((relu(total)-r)/TAU)
// total[:,0:NE]  = r_e @ W_ee + r_i @ W_ie + unit_input_e
// total[:,NE:NU] = r_e @ W_ei + r_i @ W_ii + unit_input_i + inter
// inter[i,a] = sum_{j,b} W_inter[i,j,a,b] * r[i, NE+b]
//
// R9: R5 structure with LPT-style block ordering (long partial blocks first,
// short inter blocks last) and P_SLICES=16 for near-uniform block lengths.

#define N_NET 32
#define NU 2048
#define NE 1638
#define NI 410
#define DT 0.01f
#define TAU 0.1f

#define P_SLICES 16
#define P_PER_SLICE (NU / P_SLICES)             // 128

#define PARTIAL_BLOCKS (16 * P_SLICES * N_NET)  // 8192
#define INTER_BLOCKS (N_NET * NI)               // 13120
#define TOTAL_BLOCKS (PARTIAL_BLOCKS + INTER_BLOCKS)  // 21312

__device__ float g_inter[N_NET * NI];
__device__ float g_partial[P_SLICES * N_NET * NU];   // [slice][net][q], 4 MB

// ---------------------------------------------------------------------------
// Fused streaming kernel:
//   blocks [0, PARTIAL_BLOCKS)          : partial GEMV sums (longer blocks)
//   blocks [PARTIAL_BLOCKS, TOTAL)      : inter[i,a]       (shorter blocks)
// ---------------------------------------------------------------------------
__global__ void __launch_bounds__(128) fused_kernel(
    const float* __restrict__ r,
    const float* __restrict__ W_ee,
    const float* __restrict__ W_ei,
    const float* __restrict__ W_ie,
    const float* __restrict__ W_ii,
    const float* __restrict__ W_inter)
{
    __shared__ float rs[NI + 8];
    __shared__ float red[4];

    const int bx  = blockIdx.x;
    const int tid = threadIdx.x;

    if (bx >= PARTIAL_BLOCKS) {
        // ----------------- inter role -----------------
        const int bi = bx - PARTIAL_BLOCKS;
        const int a = bi % NI;
        const int i = bi / NI;

        const float* ri = r + (size_t)i * NU + NE;
        for (int b = tid; b < NI; b += 128) rs[b] = ri[b];
        __syncthreads();

        const float* base = W_inter + (size_t)i * N_NET * (NI * NI) + (size_t)a * NI;

        float acc = 0.f;
        for (int t = tid; t < NI / 2; t += 128) {
            const float x = rs[2 * t];
            const float y = rs[2 * t + 1];
            #pragma unroll 8
            for (int j = 0; j < N_NET; ++j) {
                const float2 w = *(const float2*)(base + (size_t)j * (NI * NI) + 2 * t);
                acc = fmaf(w.x, x, acc);
                acc = fmaf(w.y, y, acc);
            }
        }

        #pragma unroll
        for (int o = 16; o > 0; o >>= 1)
            acc += __shfl_down_sync(0xFFFFFFFFu, acc, o);
        if ((tid & 31) == 0) red[tid >> 5] = acc;
        __syncthreads();
        if (tid == 0)
            g_inter[i * NI + a] = red[0] + red[1] + red[2] + red[3];
    } else {
        // ----------------- partial GEMV role -----------------
        const int qt  = bx & 15;                   // q tile (16)
        const int ps  = (bx >> 4) & (P_SLICES - 1); // p slice (16)
        const int n   = bx >> 8;                   // net (32)

        const int q  = qt * 128 + tid;     // 0..2047
        const int pa = ps * P_PER_SLICE;
        const int pb = pa + P_PER_SLICE;

        rs[tid] = r[(size_t)n * NU + pa + tid];
        __syncthreads();

        const float* colE;
        const float* colI;
        int stride;
        if (q < NE) {
            stride = NE;
            colE = W_ee + (size_t)n * NE * NE + q;
            colI = W_ie + (size_t)n * NI * NE + q;
        } else {
            const int qq = q - NE;
            stride = NI;
            colE = W_ei + (size_t)n * NE * NI + qq;
            colI = W_ii + (size_t)n * NI * NI + qq;
        }

        float acc = 0.f;

        // rows p in [pa, min(pb, NE)) from the E-row matrix
        {
            const int pe = (pb < NE) ? pb : NE;
            int p = pa;
            for (; p + 8 <= pe; p += 8) {
                const float w0 = colE[(size_t)(p + 0) * stride];
                const float w1 = colE[(size_t)(p + 1) * stride];
                const float w2 = colE[(size_t)(p + 2) * stride];
                const float w3 = colE[(size_t)(p + 3) * stride];
                const float w4 = colE[(size_t)(p + 4) * stride];
                const float w5 = colE[(size_t)(p + 5) * stride];
                const float w6 = colE[(size_t)(p + 6) * stride];
                const float w7 = colE[(size_t)(p + 7) * stride];
                const int t = p - pa;
                acc = fmaf(w0, rs[t + 0], acc);
                acc = fmaf(w1, rs[t + 1], acc);
                acc = fmaf(w2, rs[t + 2], acc);
                acc = fmaf(w3, rs[t + 3], acc);
                acc = fmaf(w4, rs[t + 4], acc);
                acc = fmaf(w5, rs[t + 5], acc);
                acc = fmaf(w6, rs[t + 6], acc);
                acc = fmaf(w7, rs[t + 7], acc);
            }
            for (; p < pe; ++p)
                acc = fmaf(colE[(size_t)p * stride], rs[p - pa], acc);
        }

        // rows p in [max(pa, NE), pb) from the I-row matrix
        {
            const int p0 = (pa > NE) ? pa : NE;
            int p = p0;
            for (; p + 8 <= pb; p += 8) {
                const float w0 = colI[(size_t)(p - NE + 0) * stride];
                const float w1 = colI[(size_t)(p - NE + 1) * stride];
                const float w2 = colI[(size_t)(p - NE + 2) * stride];
                const float w3 = colI[(size_t)(p - NE + 3) * stride];
                const float w4 = colI[(size_t)(p - NE + 4) * stride];
                const float w5 = colI[(size_t)(p - NE + 5) * stride];
                const float w6 = colI[(size_t)(p - NE + 6) * stride];
                const float w7 = colI[(size_t)(p - NE + 7) * stride];
                const int t = p - pa;
                acc = fmaf(w0, rs[t + 0], acc);
                acc = fmaf(w1, rs[t + 1], acc);
                acc = fmaf(w2, rs[t + 2], acc);
                acc = fmaf(w3, rs[t + 3], acc);
                acc = fmaf(w4, rs[t + 4], acc);
                acc = fmaf(w5, rs[t + 5], acc);
                acc = fmaf(w6, rs[t + 6], acc);
                acc = fmaf(w7, rs[t + 7], acc);
            }
            for (; p < pb; ++p)
                acc = fmaf(colI[(size_t)(p - NE) * stride], rs[p - pa], acc);
        }

        g_partial[((size_t)ps * N_NET + n) * NU + q] = acc;
    }

#if __CUDA_ARCH__ >= 900
    cudaTriggerProgrammaticLaunchCompletion();
#endif
}

// ---------------------------------------------------------------------------
// Reduce 16 partials + unit_input (+inter for inhibitory) + epilogue.
// PDL-launched: prefetch primary-independent inputs, then grid-dep sync.
// ---------------------------------------------------------------------------
__global__ void __launch_bounds__(1024) reduce_kernel(
    const float* __restrict__ unit_input,
    const float* __restrict__ r,
    float* __restrict__ out)
{
    const int idx = blockIdx.x * 1024 + threadIdx.x;   // 0..65535
    const int n = idx >> 11;
    const int q = idx & 2047;

    const float ui = unit_input[idx];
    const float rv = r[idx];

#if __CUDA_ARCH__ >= 900
    cudaGridDependencySynchronize();
#endif

    float acc = 0.f;
    #pragma unroll
    for (int s = 0; s < P_SLICES; ++s)
        acc += g_partial[((size_t)s * N_NET + n) * NU + q];

    acc += ui;
    if (q >= NE) acc += g_inter[n * NI + (q - NE)];

    const float phi = fmaxf(acc, 0.f);
    out[idx] = rv + DT * ((phi - rv) / TAU);
}

extern "C" void kernel_launch(void* const* d_in, const int* in_sizes, int n_in,
                              void* d_out, int out_size)
{
    const float* unit_input = (const float*)d_in[0];
    const float* r          = (const float*)d_in[1];
    const float* W_ee       = (const float*)d_in[2];
    const float* W_ei       = (const float*)d_in[3];
    const float* W_ie       = (const float*)d_in[4];
    const float* W_ii       = (const float*)d_in[5];
    const float* W_inter    = (const float*)d_in[6];
    float* out = (float*)d_out;

    fused_kernel<<<TOTAL_BLOCKS, 128>>>(r, W_ee, W_ei, W_ie, W_ii, W_inter);

    cudaLaunchConfig_t cfg = {};
    cfg.gridDim  = dim3(64, 1, 1);
    cfg.blockDim = dim3(1024, 1, 1);
    cfg.dynamicSmemBytes = 0;
    cfg.stream = 0;
    cudaLaunchAttribute attrs[1];
    attrs[0].id = cudaLaunchAttributeProgrammaticStreamSerialization;
    attrs[0].val.programmaticStreamSerializationAllowed = 1;
    cfg.attrs = attrs;
    cfg.numAttrs = 1;
    cudaLaunchKernelEx(&cfg, reduce_kernel, unit_input, r, out);
}

// round 10
// speedup vs baseline: 1.2526x; 1.0266x over previous
#include <cuda_runtime.h>
#include <cuda_bf16.h>
#include <cstddef>

// MultiNetworkRNN: N_NET=32, N_UNITS=2048, N_EXC=1638, N_INH=410
// out[n,q] = r + DT*((relu(total)-r)/TAU)
// total[:,0:NE]  = r_e @ W_ee + r_i @ W_ie + unit_input_e
// total[:,NE:NU] = r_e @ W_ei + r_i @ W_ii + unit_input_i + inter
// inter[i,a] = sum_{j,b} W_inter[i,j,a,b] * r[i, NE+b]
//
// R10: R9 (best: 185.1us) + __ldcs streaming hints on all read-once weight
// loads, keeping g_partial / r resident in L2 for the PDL reduce.

#define N_NET 32
#define NU 2048
#define NE 1638
#define NI 410
#define DT 0.01f
#define TAU 0.1f

#define P_SLICES 16
#define P_PER_SLICE (NU / P_SLICES)             // 128

#define PARTIAL_BLOCKS (16 * P_SLICES * N_NET)  // 8192
#define INTER_BLOCKS (N_NET * NI)               // 13120
#define TOTAL_BLOCKS (PARTIAL_BLOCKS + INTER_BLOCKS)  // 21312

__device__ float g_inter[N_NET * NI];
__device__ float g_partial[P_SLICES * N_NET * NU];   // [slice][net][q], 4 MB

// ---------------------------------------------------------------------------
// Fused streaming kernel:
//   blocks [0, PARTIAL_BLOCKS)          : partial GEMV sums (longer blocks)
//   blocks [PARTIAL_BLOCKS, TOTAL)      : inter[i,a]       (shorter blocks)
// ---------------------------------------------------------------------------
__global__ void __launch_bounds__(128) fused_kernel(
    const float* __restrict__ r,
    const float* __restrict__ W_ee,
    const float* __restrict__ W_ei,
    const float* __restrict__ W_ie,
    const float* __restrict__ W_ii,
    const float* __restrict__ W_inter)
{
    __shared__ float rs[NI + 8];
    __shared__ float red[4];

    const int bx  = blockIdx.x;
    const int tid = threadIdx.x;

    if (bx >= PARTIAL_BLOCKS) {
        // ----------------- inter role -----------------
        const int bi = bx - PARTIAL_BLOCKS;
        const int a = bi % NI;
        const int i = bi / NI;

        const float* ri = r + (size_t)i * NU + NE;
        for (int b = tid; b < NI; b += 128) rs[b] = ri[b];
        __syncthreads();

        const float* base = W_inter + (size_t)i * N_NET * (NI * NI) + (size_t)a * NI;

        float acc = 0.f;
        for (int t = tid; t < NI / 2; t += 128) {
            const float x = rs[2 * t];
            const float y = rs[2 * t + 1];
            #pragma unroll 8
            for (int j = 0; j < N_NET; ++j) {
                const float2 w = __ldcs((const float2*)(base + (size_t)j * (NI * NI) + 2 * t));
                acc = fmaf(w.x, x, acc);
                acc = fmaf(w.y, y, acc);
            }
        }

        #pragma unroll
        for (int o = 16; o > 0; o >>= 1)
            acc += __shfl_down_sync(0xFFFFFFFFu, acc, o);
        if ((tid & 31) == 0) red[tid >> 5] = acc;
        __syncthreads();
        if (tid == 0)
            g_inter[i * NI + a] = red[0] + red[1] + red[2] + red[3];
    } else {
        // ----------------- partial GEMV role -----------------
        const int qt  = bx & 15;                    // q tile (16)
        const int ps  = (bx >> 4) & (P_SLICES - 1); // p slice (16)
        const int n   = bx >> 8;                    // net (32)

        const int q  = qt * 128 + tid;     // 0..2047
        const int pa = ps * P_PER_SLICE;
        const int pb = pa + P_PER_SLICE;

        rs[tid] = r[(size_t)n * NU + pa + tid];
        __syncthreads();

        const float* colE;
        const float* colI;
        int stride;
        if (q < NE) {
            stride = NE;
            colE = W_ee + (size_t)n * NE * NE + q;
            colI = W_ie + (size_t)n * NI * NE + q;
        } else {
            const int qq = q - NE;
            stride = NI;
            colE = W_ei + (size_t)n * NE * NI + qq;
            colI = W_ii + (size_t)n * NI * NI + qq;
        }

        float acc = 0.f;

        // rows p in [pa, min(pb, NE)) from the E-row matrix
        {
            const int pe = (pb < NE) ? pb : NE;
            int p = pa;
            for (; p + 8 <= pe; p += 8) {
                const float w0 = __ldcs(colE + (size_t)(p + 0) * stride);
                const float w1 = __ldcs(colE + (size_t)(p + 1) * stride);
                const float w2 = __ldcs(colE + (size_t)(p + 2) * stride);
                const float w3 = __ldcs(colE + (size_t)(p + 3) * stride);
                const float w4 = __ldcs(colE + (size_t)(p + 4) * stride);
                const float w5 = __ldcs(colE + (size_t)(p + 5) * stride);
                const float w6 = __ldcs(colE + (size_t)(p + 6) * stride);
                const float w7 = __ldcs(colE + (size_t)(p + 7) * stride);
                const int t = p - pa;
                acc = fmaf(w0, rs[t + 0], acc);
                acc = fmaf(w1, rs[t + 1], acc);
                acc = fmaf(w2, rs[t + 2], acc);
                acc = fmaf(w3, rs[t + 3], acc);
                acc = fmaf(w4, rs[t + 4], acc);
                acc = fmaf(w5, rs[t + 5], acc);
                acc = fmaf(w6, rs[t + 6], acc);
                acc = fmaf(w7, rs[t + 7], acc);
            }
            for (; p < pe; ++p)
                acc = fmaf(__ldcs(colE + (size_t)p * stride), rs[p - pa], acc);
        }

        // rows p in [max(pa, NE), pb) from the I-row matrix
        {
            const int p0 = (pa > NE) ? pa : NE;
            int p = p0;
            for (; p + 8 <= pb; p += 8) {
                const float w0 = __ldcs(colI + (size_t)(p - NE + 0) * stride);
                const float w1 = __ldcs(colI + (size_t)(p - NE + 1) * stride);
                const float w2 = __ldcs(colI + (size_t)(p - NE + 2) * stride);
                const float w3 = __ldcs(colI + (size_t)(p - NE + 3) * stride);
                const float w4 = __ldcs(colI + (size_t)(p - NE + 4) * stride);
                const float w5 = __ldcs(colI + (size_t)(p - NE + 5) * stride);
                const float w6 = __ldcs(colI + (size_t)(p - NE + 6) * stride);
                const float w7 = __ldcs(colI + (size_t)(p - NE + 7) * stride);
                const int t = p - pa;
                acc = fmaf(w0, rs[t + 0], acc);
                acc = fmaf(w1, rs[t + 1], acc);
                acc = fmaf(w2, rs[t + 2], acc);
                acc = fmaf(w3, rs[t + 3], acc);
                acc = fmaf(w4, rs[t + 4], acc);
                acc = fmaf(w5, rs[t + 5], acc);
                acc = fmaf(w6, rs[t + 6], acc);
                acc = fmaf(w7, rs[t + 7], acc);
            }
            for (; p < pb; ++p)
                acc = fmaf(__ldcs(colI + (size_t)(p - NE) * stride), rs[p - pa], acc);
        }

        g_partial[((size_t)ps * N_NET + n) * NU + q] = acc;
    }

#if __CUDA_ARCH__ >= 900
    cudaTriggerProgrammaticLaunchCompletion();
#endif
}

// ---------------------------------------------------------------------------
// Reduce 16 partials + unit_input (+inter for inhibitory) + epilogue.
// PDL-launched: prefetch primary-independent inputs, then grid-dep sync.
// ---------------------------------------------------------------------------
__global__ void __launch_bounds__(1024) reduce_kernel(
    const float* __restrict__ unit_input,
    const float* __restrict__ r,
    float* __restrict__ out)
{
    const int idx = blockIdx.x * 1024 + threadIdx.x;   // 0..65535
    const int n = idx >> 11;
    const int q = idx & 2047;

    const float ui = unit_input[idx];
    const float rv = r[idx];

#if __CUDA_ARCH__ >= 900
    cudaGridDependencySynchronize();
#endif

    float acc = 0.f;
    #pragma unroll
    for (int s = 0; s < P_SLICES; ++s)
        acc += g_partial[((size_t)s * N_NET + n) * NU + q];

    acc += ui;
    if (q >= NE) acc += g_inter[n * NI + (q - NE)];

    const float phi = fmaxf(acc, 0.f);
    out[idx] = rv + DT * ((phi - rv) / TAU);
}

extern "C" void kernel_launch(void* const* d_in, const int* in_sizes, int n_in,
                              void* d_out, int out_size)
{
    const float* unit_input = (const float*)d_in[0];
    const float* r          = (const float*)d_in[1];
    const float* W_ee       = (const float*)d_in[2];
    const float* W_ei       = (const float*)d_in[3];
    const float* W_ie       = (const float*)d_in[4];
    const float* W_ii       = (const float*)d_in[5];
    const float* W_inter    = (const float*)d_in[6];
    float* out = (float*)d_out;

    fused_kernel<<<TOTAL_BLOCKS, 128>>>(r, W_ee, W_ei, W_ie, W_ii, W_inter);

    cudaLaunchConfig_t cfg = {};
    cfg.gridDim  = dim3(64, 1, 1);
    cfg.blockDim = dim3(1024, 1, 1);
    cfg.dynamicSmemBytes = 0;
    cfg.stream = 0;
    cudaLaunchAttribute attrs[1];
    attrs[0].id = cudaLaunchAttributeProgrammaticStreamSerialization;
    attrs[0].val.programmaticStreamSerializationAllowed = 1;
    cfg.attrs = attrs;
    cfg.numAttrs = 1;
    cudaLaunchKernelEx(&cfg, reduce_kernel, unit_input, r, out);
}